// round 4
// baseline (speedup 1.0000x reference)
#include <cuda_runtime.h>
#include <math.h>
#include <stdint.h>

#define D_MODEL 1024
#define NUM_HEADS 16
#define DK 64
#define BATCH 2
#define SEQ 2048
#define M_TOTAL (BATCH * SEQ)  // 4096

// flash packed-layout constants
#define KV_LANE_STRIDE 20            // words per lane (16 data + 4 pad) -> conflict-free
#define KV_J_STRIDE    (32 * KV_LANE_STRIDE)  // 640 words per 8-col tile
#define KV_MAT_WORDS   (8 * KV_J_STRIDE)      // 5120 words = 20KB
#define P_LANE_STRIDE  36            // 32 data + 4 pad
#define P_WARP_WORDS   (32 * P_LANE_STRIDE)   // 1152 words

__device__ float g_q[BATCH * NUM_HEADS * SEQ * DK];   // pre-scaled (1/8), tf32-rounded
__device__ float g_k[BATCH * NUM_HEADS * SEQ * DK];   // tf32-rounded
__device__ float g_v[BATCH * NUM_HEADS * SEQ * DK];   // tf32-rounded
__device__ float g_cat[M_TOTAL * D_MODEL];

__device__ __forceinline__ uint32_t f2tf(float f) {
    uint32_t u;
    asm("cvt.rna.tf32.f32 %0, %1;" : "=r"(u) : "f"(f));
    return u;
}

__device__ __forceinline__ void mma_tf32(float* c, const uint32_t* a, const uint32_t* b) {
    asm volatile(
        "mma.sync.aligned.m16n8k8.row.col.f32.tf32.tf32.f32 "
        "{%0,%1,%2,%3}, {%4,%5,%6,%7}, {%8,%9}, {%0,%1,%2,%3};"
        : "+f"(c[0]), "+f"(c[1]), "+f"(c[2]), "+f"(c[3])
        : "r"(a[0]), "r"(a[1]), "r"(a[2]), "r"(a[3]), "r"(b[0]), "r"(b[1]));
}
__device__ __forceinline__ void mma_tf32_v(float* c, const uint32_t* a, uint32_t b0, uint32_t b1) {
    asm volatile(
        "mma.sync.aligned.m16n8k8.row.col.f32.tf32.tf32.f32 "
        "{%0,%1,%2,%3}, {%4,%5,%6,%7}, {%8,%9}, {%0,%1,%2,%3};"
        : "+f"(c[0]), "+f"(c[1]), "+f"(c[2]), "+f"(c[3])
        : "r"(a[0]), "r"(a[1]), "r"(a[2]), "r"(a[3]), "r"(b0), "r"(b1));
}

// =====================================================================
// Merged projection GEMMs (Q,K,V): z = blockIdx.z selects problem.
// out[b,h,s,kd] = X[m,:] @ W[h,:,kd] + bias ; epilogue tf32-rounds
// (and scales Q by 1/8).
// =====================================================================
struct ProjArgs {
    const float* X[3];
    const float* W[3];
    const float* bias[3];
    float* out[3];
};

__global__ __launch_bounds__(256) void proj_gemm3_kernel(ProjArgs args)
{
    __shared__ uint32_t As[2][16 * 136];
    __shared__ uint32_t Bs[2][16 * 136];

    const int z    = blockIdx.z;
    const float* X    = args.X[z];
    const float* W    = args.W[z];
    const float* bias = args.bias[z];
    float* out        = args.out[z];
    const float escale = (z == 0) ? 0.125f : 1.0f;

    const int t    = threadIdx.x;
    const int n0   = blockIdx.x * 128;
    const int m0   = blockIdx.y * 128;
    const int warp = t >> 5;
    const int lane = t & 31;
    const int gid  = lane >> 2;
    const int tig  = lane & 3;
    const int wm   = (warp & 1) * 64;
    const int wn   = (warp >> 1) * 32;

    float acc[4][4][4];
#pragma unroll
    for (int i = 0; i < 4; i++)
#pragma unroll
        for (int j = 0; j < 4; j++)
#pragma unroll
            for (int k = 0; k < 4; k++) acc[i][j][k] = 0.f;

    float4 ar[2], br[2];

    auto loadA = [&](int kc) {
#pragma unroll
        for (int rep = 0; rep < 2; rep++) {
            int f = t + rep * 256;
            int m = f >> 2, c4 = (f & 3) << 2;
            ar[rep] = *(const float4*)(X + (size_t)(m0 + m) * D_MODEL + kc * 16 + c4);
        }
    };
    auto storeA = [&](int buf) {
#pragma unroll
        for (int rep = 0; rep < 2; rep++) {
            int f = t + rep * 256;
            int m = f >> 2, c4 = (f & 3) << 2;
            int col = m ^ c4;
            As[buf][(c4 + 0) * 136 + col] = f2tf(ar[rep].x);
            As[buf][(c4 + 1) * 136 + col] = f2tf(ar[rep].y);
            As[buf][(c4 + 2) * 136 + col] = f2tf(ar[rep].z);
            As[buf][(c4 + 3) * 136 + col] = f2tf(ar[rep].w);
        }
    };
    auto loadB = [&](int kc) {
#pragma unroll
        for (int rep = 0; rep < 2; rep++) {
            int f = t + rep * 256;
            int k = f >> 5, n4 = (f & 31) << 2;
            int bn = n0 + n4;
            br[rep] = *(const float4*)(W + (size_t)(bn >> 6) * (D_MODEL * DK)
                                         + (size_t)(kc * 16 + k) * DK + (bn & 63));
        }
    };
    auto storeB = [&](int buf) {
#pragma unroll
        for (int rep = 0; rep < 2; rep++) {
            int f = t + rep * 256;
            int k = f >> 5, n4 = (f & 31) << 2;
            int ck = ((k >> 2) & 3) << 2;
            uint32_t* p = &Bs[buf][k * 136 + (n4 ^ ck)];
            p[0] = f2tf(br[rep].x);
            p[1] = f2tf(br[rep].y);
            p[2] = f2tf(br[rep].z);
            p[3] = f2tf(br[rep].w);
        }
    };
    auto compute = [&](int buf) {
#pragma unroll
        for (int ks = 0; ks < 2; ks++) {
            const int kb = ks * 8;
            const int x0 = ks ? 8 : 0;
            const int x1 = ks ? 12 : 4;
            uint32_t af[4][4];
#pragma unroll
            for (int mt = 0; mt < 4; mt++) {
                int mrow = wm + mt * 16 + gid;
                af[mt][0] = As[buf][(kb + tig) * 136 + (mrow ^ x0)];
                af[mt][1] = As[buf][(kb + tig) * 136 + ((mrow + 8) ^ x0)];
                af[mt][2] = As[buf][(kb + tig + 4) * 136 + (mrow ^ x1)];
                af[mt][3] = As[buf][(kb + tig + 4) * 136 + ((mrow + 8) ^ x1)];
            }
            uint32_t bf[4][2];
#pragma unroll
            for (int nt = 0; nt < 4; nt++) {
                int ncol = wn + nt * 8 + gid;
                bf[nt][0] = Bs[buf][(kb + tig) * 136 + (ncol ^ x0)];
                bf[nt][1] = Bs[buf][(kb + tig + 4) * 136 + (ncol ^ x1)];
            }
#pragma unroll
            for (int mt = 0; mt < 4; mt++)
#pragma unroll
                for (int nt = 0; nt < 4; nt++) mma_tf32(acc[mt][nt], af[mt], bf[nt]);
        }
    };

    loadA(0); loadB(0);
    storeA(0); storeB(0);
    __syncthreads();
    int buf = 0;
    for (int kc = 0; kc < 64; kc++) {
        if (kc < 63) { loadA(kc + 1); loadB(kc + 1); }
        compute(buf);
        if (kc < 63) { storeA(buf ^ 1); storeB(buf ^ 1); }
        __syncthreads();
        buf ^= 1;
    }

#pragma unroll
    for (int mt = 0; mt < 4; mt++) {
#pragma unroll
        for (int nt = 0; nt < 4; nt++) {
            const int r0 = m0 + wm + mt * 16 + gid;
            const int r1 = r0 + 8;
            const int c  = n0 + wn + nt * 8 + tig * 2;
            const float bv0 = bias[c], bv1 = bias[c + 1];
            float2 v0, v1;
            v0.x = __uint_as_float(f2tf((acc[mt][nt][0] + bv0) * escale));
            v0.y = __uint_as_float(f2tf((acc[mt][nt][1] + bv1) * escale));
            v1.x = __uint_as_float(f2tf((acc[mt][nt][2] + bv0) * escale));
            v1.y = __uint_as_float(f2tf((acc[mt][nt][3] + bv1) * escale));
            const int h = c >> 6, kd = c & 63;
            const int b0_ = r0 >> 11, s0 = r0 & 2047;
            const int b1_ = r1 >> 11, s1 = r1 & 2047;
            *(float2*)(out + (((size_t)b0_ * NUM_HEADS + h) * SEQ + s0) * DK + kd) = v0;
            *(float2*)(out + (((size_t)b1_ * NUM_HEADS + h) * SEQ + s1) * DK + kd) = v1;
        }
    }
}

// =====================================================================
// Output projection GEMM: out[m,n] = cat[m,:] @ Wo[n,:]^T + bo (fp32 out)
// =====================================================================
__global__ __launch_bounds__(256) void out_gemm_kernel(
    const float* __restrict__ X, const float* __restrict__ W,
    const float* __restrict__ bias, float* __restrict__ out)
{
    __shared__ uint32_t As[2][16 * 136];
    __shared__ uint32_t Bs[2][16 * 136];

    const int t    = threadIdx.x;
    const int n0   = blockIdx.x * 128;
    const int m0   = blockIdx.y * 128;
    const int warp = t >> 5;
    const int lane = t & 31;
    const int gid  = lane >> 2;
    const int tig  = lane & 3;
    const int wm   = (warp & 1) * 64;
    const int wn   = (warp >> 1) * 32;

    float acc[4][4][4];
#pragma unroll
    for (int i = 0; i < 4; i++)
#pragma unroll
        for (int j = 0; j < 4; j++)
#pragma unroll
            for (int k = 0; k < 4; k++) acc[i][j][k] = 0.f;

    float4 ar[2], br[2];

    auto loadA = [&](int kc) {
#pragma unroll
        for (int rep = 0; rep < 2; rep++) {
            int f = t + rep * 256;
            int m = f >> 2, c4 = (f & 3) << 2;
            ar[rep] = *(const float4*)(X + (size_t)(m0 + m) * D_MODEL + kc * 16 + c4);
        }
    };
    auto storeA = [&](int buf) {
#pragma unroll
        for (int rep = 0; rep < 2; rep++) {
            int f = t + rep * 256;
            int m = f >> 2, c4 = (f & 3) << 2;
            int col = m ^ c4;
            As[buf][(c4 + 0) * 136 + col] = f2tf(ar[rep].x);
            As[buf][(c4 + 1) * 136 + col] = f2tf(ar[rep].y);
            As[buf][(c4 + 2) * 136 + col] = f2tf(ar[rep].z);
            As[buf][(c4 + 3) * 136 + col] = f2tf(ar[rep].w);
        }
    };
    auto loadB = [&](int kc) {
#pragma unroll
        for (int rep = 0; rep < 2; rep++) {
            int f = t + rep * 256;
            int n = f >> 2, k4 = (f & 3) << 2;
            br[rep] = *(const float4*)(W + (size_t)(n0 + n) * D_MODEL + kc * 16 + k4);
        }
    };
    auto storeB = [&](int buf) {
#pragma unroll
        for (int rep = 0; rep < 2; rep++) {
            int f = t + rep * 256;
            int n = f >> 2, k4 = (f & 3) << 2;
            int col = n ^ k4;
            Bs[buf][(k4 + 0) * 136 + col] = f2tf(br[rep].x);
            Bs[buf][(k4 + 1) * 136 + col] = f2tf(br[rep].y);
            Bs[buf][(k4 + 2) * 136 + col] = f2tf(br[rep].z);
            Bs[buf][(k4 + 3) * 136 + col] = f2tf(br[rep].w);
        }
    };
    auto compute = [&](int buf) {
#pragma unroll
        for (int ks = 0; ks < 2; ks++) {
            const int kb = ks * 8;
            const int x0 = ks ? 8 : 0;
            const int x1 = ks ? 12 : 4;
            uint32_t af[4][4];
#pragma unroll
            for (int mt = 0; mt < 4; mt++) {
                int mrow = wm + mt * 16 + gid;
                af[mt][0] = As[buf][(kb + tig) * 136 + (mrow ^ x0)];
                af[mt][1] = As[buf][(kb + tig) * 136 + ((mrow + 8) ^ x0)];
                af[mt][2] = As[buf][(kb + tig + 4) * 136 + (mrow ^ x1)];
                af[mt][3] = As[buf][(kb + tig + 4) * 136 + ((mrow + 8) ^ x1)];
            }
            uint32_t bf[4][2];
#pragma unroll
            for (int nt = 0; nt < 4; nt++) {
                int ncol = wn + nt * 8 + gid;
                bf[nt][0] = Bs[buf][(kb + tig) * 136 + (ncol ^ x0)];
                bf[nt][1] = Bs[buf][(kb + tig + 4) * 136 + (ncol ^ x1)];
            }
#pragma unroll
            for (int mt = 0; mt < 4; mt++)
#pragma unroll
                for (int nt = 0; nt < 4; nt++) mma_tf32(acc[mt][nt], af[mt], bf[nt]);
        }
    };

    loadA(0); loadB(0);
    storeA(0); storeB(0);
    __syncthreads();
    int buf = 0;
    for (int kc = 0; kc < 64; kc++) {
        if (kc < 63) { loadA(kc + 1); loadB(kc + 1); }
        compute(buf);
        if (kc < 63) { storeA(buf ^ 1); storeB(buf ^ 1); }
        __syncthreads();
        buf ^= 1;
    }

#pragma unroll
    for (int mt = 0; mt < 4; mt++) {
#pragma unroll
        for (int nt = 0; nt < 4; nt++) {
            const int r0 = m0 + wm + mt * 16 + gid;
            const int r1 = r0 + 8;
            const int c  = n0 + wn + nt * 8 + tig * 2;
            const float bv0 = bias[c], bv1 = bias[c + 1];
            float2 v0 = make_float2(acc[mt][nt][0] + bv0, acc[mt][nt][1] + bv1);
            float2 v1 = make_float2(acc[mt][nt][2] + bv0, acc[mt][nt][3] + bv1);
            *(float2*)(out + (size_t)r0 * D_MODEL + c) = v0;
            *(float2*)(out + (size_t)r1 * D_MODEL + c) = v1;
        }
    }
}

// =====================================================================
// Flash attention v4: packed mma-fragment smem layouts (LDS.128 gathers),
// pre-rounded tf32 inputs, 2 blocks/SM.
// Bq=128 (8 warps x 16 rows), Bkv=64.
//
// K/V packed layout (B-fragment order, m16n8k8.row.col):
//   word(n,k) -> addr = (n>>3)*640 + ((n&7)*4 + (k&3))*20 + (k>>3)*2 + ((k>>2)&1)
//   (for K: n = kv index, k = d; for V: n = d, k = kv)
//   Consumer lane loads uint4 at j*640 + lane*20 + g*4  ->
//   {kk=2g:b0, kk=2g:b1, kk=2g+1:b0, kk=2g+1:b1}
// P packed layout (A-fragment order), per-warp:
//   word(row,k) -> addr = ((row&7)*4 + (k&3))*36 + (k>>3)*4 + (row>=8) + 2*((k>>2)&1)
//   Consumer lane loads uint4 at lane*36 + kk*4 -> {a0,a1,a2,a3}
// =====================================================================
__global__ __launch_bounds__(256, 2) void flash_mma_kernel()
{
    extern __shared__ uint32_t smu[];
    uint32_t* Ks = smu;                        // 5120 words
    uint32_t* Vs = smu + KV_MAT_WORDS;         // 5120 words
    uint32_t* Ps = smu + 2 * KV_MAT_WORDS;     // 8*1152 words

    const int t    = threadIdx.x;
    const int warp = t >> 5;
    const int lane = t & 31;
    const int gid  = lane >> 2;
    const int tig  = lane & 3;
    const int q0   = blockIdx.x * 128;
    const int bh   = blockIdx.y;

    const float* qb = g_q + (size_t)bh * SEQ * DK;
    const float* kb = g_k + (size_t)bh * SEQ * DK;
    const float* vb = g_v + (size_t)bh * SEQ * DK;

    // Q fragments (pre-scaled, pre-rounded in proj epilogue)
    const int r0 = q0 + warp * 16 + gid;
    const int r1 = r0 + 8;
    uint32_t qf[8][4];
#pragma unroll
    for (int kk = 0; kk < 8; kk++) {
        qf[kk][0] = __float_as_uint(qb[(size_t)r0 * DK + kk * 8 + tig]);
        qf[kk][1] = __float_as_uint(qb[(size_t)r1 * DK + kk * 8 + tig]);
        qf[kk][2] = __float_as_uint(qb[(size_t)r0 * DK + kk * 8 + tig + 4]);
        qf[kk][3] = __float_as_uint(qb[(size_t)r1 * DK + kk * 8 + tig + 4]);
    }

    uint32_t* Pw = Ps + warp * P_WARP_WORDS;
    // P store addresses (constant per thread, + j*4 / +1 offsets)
    const int e0a = (gid * 4 + ((2 * tig) & 3)) * P_LANE_STRIDE + 2 * (tig >= 2);
    const int e1a = (gid * 4 + ((2 * tig + 1) & 3)) * P_LANE_STRIDE + 2 * (tig >= 2);

    float m0 = -INFINITY, m1 = -INFINITY, l0 = 0.f, l1 = 0.f;
    float o[8][4];
#pragma unroll
    for (int j = 0; j < 8; j++)
#pragma unroll
        for (int k = 0; k < 4; k++) o[j][k] = 0.f;

    for (int s0 = 0; s0 < SEQ; s0 += 64) {
        __syncthreads();
        // load K,V tile (64 rows x 64 cols) into packed layouts
#pragma unroll
        for (int rep = 0; rep < 4; rep++) {
            int f = t + rep * 256;
            int row = f >> 4, c4 = (f & 15) << 2;
            float4 kv4 = *(const float4*)&kb[(size_t)(s0 + row) * DK + c4];
            float4 vv4 = *(const float4*)&vb[(size_t)(s0 + row) * DK + c4];
            // K: n=row, k=c4+w ; kk,half const across w
            {
                const int jK   = row >> 3;
                const int base = jK * KV_J_STRIDE + ((row & 7) * 4) * KV_LANE_STRIDE
                               + (c4 >> 3) * 2 + ((c4 >> 2) & 1);
                Ks[base + 0 * KV_LANE_STRIDE] = __float_as_uint(kv4.x);
                Ks[base + 1 * KV_LANE_STRIDE] = __float_as_uint(kv4.y);
                Ks[base + 2 * KV_LANE_STRIDE] = __float_as_uint(kv4.z);
                Ks[base + 3 * KV_LANE_STRIDE] = __float_as_uint(kv4.w);
            }
            // V: k=row (kv), n=c4+w ; j const across w, gid8 varies
            {
                const int jV   = c4 >> 3;
                const int kkV2 = (row >> 3) * 2 + ((row >> 2) & 1);
                const int tigV = row & 3;
                const int base = jV * KV_J_STRIDE + ((c4 & 7) * 4 + tigV) * KV_LANE_STRIDE + kkV2;
                Vs[base + 0 * (4 * KV_LANE_STRIDE)] = __float_as_uint(vv4.x);
                Vs[base + 1 * (4 * KV_LANE_STRIDE)] = __float_as_uint(vv4.y);
                Vs[base + 2 * (4 * KV_LANE_STRIDE)] = __float_as_uint(vv4.z);
                Vs[base + 3 * (4 * KV_LANE_STRIDE)] = __float_as_uint(vv4.w);
            }
        }
        __syncthreads();

        // ---- S = Q K^T ----
        float sacc[8][4];
#pragma unroll
        for (int j = 0; j < 8; j++)
#pragma unroll
            for (int k = 0; k < 4; k++) sacc[j][k] = 0.f;
#pragma unroll
        for (int g = 0; g < 4; g++) {
#pragma unroll
            for (int j = 0; j < 8; j++) {
                uint4 U = *(const uint4*)&Ks[j * KV_J_STRIDE + lane * KV_LANE_STRIDE + g * 4];
                mma_tf32_v(sacc[j], qf[2 * g], U.x, U.y);
                mma_tf32_v(sacc[j], qf[2 * g + 1], U.z, U.w);
            }
        }

        // ---- fragment-resident online softmax ----
        float t0 = -INFINITY, t1 = -INFINITY;
#pragma unroll
        for (int j = 0; j < 8; j++) {
            t0 = fmaxf(t0, fmaxf(sacc[j][0], sacc[j][1]));
            t1 = fmaxf(t1, fmaxf(sacc[j][2], sacc[j][3]));
        }
        t0 = fmaxf(t0, __shfl_xor_sync(0xffffffffu, t0, 1));
        t0 = fmaxf(t0, __shfl_xor_sync(0xffffffffu, t0, 2));
        t1 = fmaxf(t1, __shfl_xor_sync(0xffffffffu, t1, 1));
        t1 = fmaxf(t1, __shfl_xor_sync(0xffffffffu, t1, 2));

        float nm0 = fmaxf(m0, t0), nm1 = fmaxf(m1, t1);
        float a0 = __expf(m0 - nm0), a1 = __expf(m1 - nm1);
        m0 = nm0; m1 = nm1;

        float p0 = 0.f, p1 = 0.f;
#pragma unroll
        for (int j = 0; j < 8; j++) {
            float e0 = __expf(sacc[j][0] - nm0);
            float e1 = __expf(sacc[j][1] - nm0);
            float e2 = __expf(sacc[j][2] - nm1);
            float e3 = __expf(sacc[j][3] - nm1);
            p0 += e0 + e1;
            p1 += e2 + e3;
            Pw[e0a + j * 4]     = f2tf(e0);
            Pw[e1a + j * 4]     = f2tf(e1);
            Pw[e0a + j * 4 + 1] = f2tf(e2);
            Pw[e1a + j * 4 + 1] = f2tf(e3);
        }
        p0 += __shfl_xor_sync(0xffffffffu, p0, 1);
        p0 += __shfl_xor_sync(0xffffffffu, p0, 2);
        p1 += __shfl_xor_sync(0xffffffffu, p1, 1);
        p1 += __shfl_xor_sync(0xffffffffu, p1, 2);
        l0 = l0 * a0 + p0;
        l1 = l1 * a1 + p1;

#pragma unroll
        for (int j = 0; j < 8; j++) {
            o[j][0] *= a0; o[j][1] *= a0;
            o[j][2] *= a1; o[j][3] *= a1;
        }
        __syncwarp();

        // ---- O += P V ----
#pragma unroll
        for (int g = 0; g < 4; g++) {
            uint4 A0 = *(const uint4*)&Pw[lane * P_LANE_STRIDE + (2 * g) * 4];
            uint4 A1 = *(const uint4*)&Pw[lane * P_LANE_STRIDE + (2 * g + 1) * 4];
            uint32_t af0[4] = {A0.x, A0.y, A0.z, A0.w};
            uint32_t af1[4] = {A1.x, A1.y, A1.z, A1.w};
#pragma unroll
            for (int j = 0; j < 8; j++) {
                uint4 U = *(const uint4*)&Vs[j * KV_J_STRIDE + lane * KV_LANE_STRIDE + g * 4];
                mma_tf32_v(o[j], af0, U.x, U.y);
                mma_tf32_v(o[j], af1, U.z, U.w);
            }
        }
    }

    // ---- epilogue ----
    const float i0 = 1.f / l0, i1 = 1.f / l1;
    const int b_ = bh >> 4, h = bh & 15;
    float* row0 = g_cat + (size_t)(b_ * SEQ + r0) * D_MODEL + h * DK;
    float* row1 = g_cat + (size_t)(b_ * SEQ + r1) * D_MODEL + h * DK;
#pragma unroll
    for (int j = 0; j < 8; j++) {
        *(float2*)(row0 + j * 8 + tig * 2) = make_float2(o[j][0] * i0, o[j][1] * i0);
        *(float2*)(row1 + j * 8 + tig * 2) = make_float2(o[j][2] * i1, o[j][3] * i1);
    }
}

extern "C" void kernel_launch(void* const* d_in, const int* in_sizes, int n_in,
                              void* d_out, int out_size)
{
    const float* Q  = (const float*)d_in[0];
    const float* K  = (const float*)d_in[1];
    const float* V  = (const float*)d_in[2];
    const float* Wq = (const float*)d_in[3];
    const float* bq = (const float*)d_in[4];
    const float* Wk = (const float*)d_in[5];
    const float* bk = (const float*)d_in[6];
    const float* Wv = (const float*)d_in[7];
    const float* bv = (const float*)d_in[8];
    const float* Wo = (const float*)d_in[9];
    const float* bo = (const float*)d_in[10];
    float* out = (float*)d_out;

    float *gq, *gk, *gv, *gcat;
    cudaGetSymbolAddress((void**)&gq, g_q);
    cudaGetSymbolAddress((void**)&gk, g_k);
    cudaGetSymbolAddress((void**)&gv, g_v);
    cudaGetSymbolAddress((void**)&gcat, g_cat);

    const int flash_smem = (2 * KV_MAT_WORDS + 8 * P_WARP_WORDS) * 4;  // 77824 B
    cudaFuncSetAttribute(flash_mma_kernel, cudaFuncAttributeMaxDynamicSharedMemorySize,
                         flash_smem);

    ProjArgs pa;
    pa.X[0] = Q;  pa.X[1] = K;  pa.X[2] = V;
    pa.W[0] = Wq; pa.W[1] = Wk; pa.W[2] = Wv;
    pa.bias[0] = bq; pa.bias[1] = bk; pa.bias[2] = bv;
    pa.out[0] = gq; pa.out[1] = gk; pa.out[2] = gv;

    dim3 gblk(256);
    dim3 pgrd(D_MODEL / 128, M_TOTAL / 128, 3);  // (8, 32, 3)
    proj_gemm3_kernel<<<pgrd, gblk>>>(pa);

    dim3 fgrd(SEQ / 128, BATCH * NUM_HEADS);     // (16, 32)
    flash_mma_kernel<<<fgrd, gblk, flash_smem>>>();

    dim3 ogrd(D_MODEL / 128, M_TOTAL / 128);     // (8, 32)
    out_gemm_kernel<<<ogrd, gblk>>>(gcat, Wo, bo, out);
}

// round 5
// speedup vs baseline: 1.3200x; 1.3200x over previous
#include <cuda_runtime.h>
#include <math.h>
#include <stdint.h>

#define D_MODEL 1024
#define NUM_HEADS 16
#define DK 64
#define BATCH 2
#define SEQ 2048
#define M_TOTAL (BATCH * SEQ)  // 4096
#define RSW 68                 // flash smem row stride (32-bit words)

// GEMM smem geometry
#define A_ROW_STRIDE 20                    // 16 k-words + 4 pad (conflict-free)
#define A_STAGE_WORDS (128 * A_ROW_STRIDE) // 2560
#define B0_STAGE_WORDS (16 * 136)          // 2176 (xor-swizzled [k][n])
#define B1_STAGE_WORDS (128 * A_ROW_STRIDE)
#define NSTAGE 3

__device__ float g_q[BATCH * NUM_HEADS * SEQ * DK];
__device__ float g_k[BATCH * NUM_HEADS * SEQ * DK];
__device__ float g_v[BATCH * NUM_HEADS * SEQ * DK];
__device__ float g_cat[M_TOTAL * D_MODEL];

__device__ __forceinline__ uint32_t f2tf(float f) {
    uint32_t u;
    asm("cvt.rna.tf32.f32 %0, %1;" : "=r"(u) : "f"(f));
    return u;
}

__device__ __forceinline__ void mma_tf32(float* c, const uint32_t* a, const uint32_t* b) {
    asm volatile(
        "mma.sync.aligned.m16n8k8.row.col.f32.tf32.tf32.f32 "
        "{%0,%1,%2,%3}, {%4,%5,%6,%7}, {%8,%9}, {%0,%1,%2,%3};"
        : "+f"(c[0]), "+f"(c[1]), "+f"(c[2]), "+f"(c[3])
        : "r"(a[0]), "r"(a[1]), "r"(a[2]), "r"(a[3]), "r"(b[0]), "r"(b[1]));
}
__device__ __forceinline__ void mma_tf32_v(float* c, const uint32_t* a, uint32_t b0, uint32_t b1) {
    asm volatile(
        "mma.sync.aligned.m16n8k8.row.col.f32.tf32.tf32.f32 "
        "{%0,%1,%2,%3}, {%4,%5,%6,%7}, {%8,%9}, {%0,%1,%2,%3};"
        : "+f"(c[0]), "+f"(c[1]), "+f"(c[2]), "+f"(c[3])
        : "r"(a[0]), "r"(a[1]), "r"(a[2]), "r"(a[3]), "r"(b0), "r"(b1));
}

__device__ __forceinline__ void cpa16(uint32_t* smem_dst, const float* gsrc) {
    uint32_t s = (uint32_t)__cvta_generic_to_shared(smem_dst);
    asm volatile("cp.async.cg.shared.global [%0], [%1], 16;" :: "r"(s), "l"(gsrc));
}
__device__ __forceinline__ void cpa_commit() {
    asm volatile("cp.async.commit_group;");
}
template <int N>
__device__ __forceinline__ void cpa_wait() {
    asm volatile("cp.async.wait_group %0;" :: "n"(N));
}

// =====================================================================
// TF32 GEMM v2: cp.async 3-stage pipeline, raw fp32 in smem (HW tf32
// truncation inside mma). 128x128 tile, K-chunk 16, 256 threads.
// MODE 0 (proj): out[b,h,s,kd] = X @ W[h] + bias ; W: [H,1024,64]
//                B smem: xor-swizzled [k][n] (16B chunks contiguous)
// MODE 1 (out):  out[m,n] = X @ Wo[n,:]^T + bo  ; Wo: [1024,1024]
//                B smem: row-major [n][k], stride 20
// A smem: row-major [m][k], stride 20.
// =====================================================================
template <int MODE>
__global__ __launch_bounds__(256, 2) void gemm_v2_kernel(
    const float* __restrict__ X, const float* __restrict__ W,
    const float* __restrict__ bias, float* __restrict__ out)
{
    extern __shared__ uint32_t sg[];
    uint32_t* smA = sg;                         // NSTAGE * A_STAGE_WORDS
    uint32_t* smB = sg + NSTAGE * A_STAGE_WORDS;
    const int BSTW = (MODE == 0) ? B0_STAGE_WORDS : B1_STAGE_WORDS;

    const int t    = threadIdx.x;
    const int n0   = blockIdx.x * 128;
    const int m0   = blockIdx.y * 128;
    const int warp = t >> 5;
    const int lane = t & 31;
    const int gid  = lane >> 2;
    const int tig  = lane & 3;
    const int wm   = (warp & 1) * 64;
    const int wn   = (warp >> 1) * 32;

    // per-thread copy coordinates (2 chunks each for A and B)
    const int am[2] = { (t + 0) >> 2, (t + 256) >> 2 };
    const int ak4   = (t & 3) << 2;

    float acc[4][4][4];
#pragma unroll
    for (int i = 0; i < 4; i++)
#pragma unroll
        for (int j = 0; j < 4; j++)
#pragma unroll
            for (int k = 0; k < 4; k++) acc[i][j][k] = 0.f;

    auto issue = [&](int stage, int kc) {
        uint32_t* As_ = smA + stage * A_STAGE_WORDS;
        uint32_t* Bs_ = smB + stage * BSTW;
#pragma unroll
        for (int rep = 0; rep < 2; rep++) {
            int m = am[rep];
            cpa16(As_ + m * A_ROW_STRIDE + ak4,
                  X + (size_t)(m0 + m) * D_MODEL + kc * 16 + ak4);
        }
#pragma unroll
        for (int rep = 0; rep < 2; rep++) {
            int f = t + rep * 256;
            if (MODE == 0) {
                int k = f >> 5, n4 = (f & 31) << 2;
                int bn = n0 + n4;
                int ck = ((k >> 2) & 3) << 2;
                cpa16(Bs_ + k * 136 + (n4 ^ ck),
                      W + (size_t)(bn >> 6) * (D_MODEL * DK)
                        + (size_t)(kc * 16 + k) * DK + (bn & 63));
            } else {
                int n = f >> 2, k4 = (f & 3) << 2;
                cpa16(Bs_ + n * A_ROW_STRIDE + k4,
                      W + (size_t)(n0 + n) * D_MODEL + kc * 16 + k4);
            }
        }
    };

    auto compute = [&](int stage) {
        uint32_t* As_ = smA + stage * A_STAGE_WORDS;
        uint32_t* Bs_ = smB + stage * BSTW;
#pragma unroll
        for (int ks = 0; ks < 2; ks++) {
            const int kb = ks * 8;
            uint32_t af[4][4];
#pragma unroll
            for (int mt = 0; mt < 4; mt++) {
                const int r = (wm + mt * 16 + gid) * A_ROW_STRIDE;
                af[mt][0] = As_[r + kb + tig];
                af[mt][1] = As_[r + 8 * A_ROW_STRIDE + kb + tig];
                af[mt][2] = As_[r + kb + tig + 4];
                af[mt][3] = As_[r + 8 * A_ROW_STRIDE + kb + tig + 4];
            }
            uint32_t bf[4][2];
#pragma unroll
            for (int nt = 0; nt < 4; nt++) {
                const int ncol = wn + nt * 8 + gid;
                if (MODE == 0) {
                    const int x0 = ks ? 8 : 0;
                    const int x1 = ks ? 12 : 4;
                    bf[nt][0] = Bs_[(kb + tig) * 136 + (ncol ^ x0)];
                    bf[nt][1] = Bs_[(kb + tig + 4) * 136 + (ncol ^ x1)];
                } else {
                    bf[nt][0] = Bs_[ncol * A_ROW_STRIDE + kb + tig];
                    bf[nt][1] = Bs_[ncol * A_ROW_STRIDE + kb + tig + 4];
                }
            }
#pragma unroll
            for (int mt = 0; mt < 4; mt++)
#pragma unroll
                for (int nt = 0; nt < 4; nt++) mma_tf32(acc[mt][nt], af[mt], bf[nt]);
        }
    };

    // 3-stage pipeline over 64 k-chunks
    issue(0, 0); cpa_commit();
    issue(1, 1); cpa_commit();
    int stage = 0;
    for (int kc = 0; kc < 64; kc++) {
        cpa_wait<1>();
        __syncthreads();
        compute(stage);
        __syncthreads();
        if (kc + 2 < 64) issue((kc + 2) % NSTAGE, kc + 2);
        cpa_commit();
        stage = (stage + 1) % NSTAGE;
    }

    // epilogue
#pragma unroll
    for (int mt = 0; mt < 4; mt++) {
#pragma unroll
        for (int nt = 0; nt < 4; nt++) {
            const int r0 = m0 + wm + mt * 16 + gid;
            const int r1 = r0 + 8;
            const int c  = n0 + wn + nt * 8 + tig * 2;
            const float bv0 = bias[c], bv1 = bias[c + 1];
            float2 v0 = make_float2(acc[mt][nt][0] + bv0, acc[mt][nt][1] + bv1);
            float2 v1 = make_float2(acc[mt][nt][2] + bv0, acc[mt][nt][3] + bv1);
            if (MODE == 0) {
                const int h = c >> 6, kd = c & 63;
                const int b0_ = r0 >> 11, s0 = r0 & 2047;
                const int b1_ = r1 >> 11, s1 = r1 & 2047;
                *(float2*)(out + (((size_t)b0_ * NUM_HEADS + h) * SEQ + s0) * DK + kd) = v0;
                *(float2*)(out + (((size_t)b1_ * NUM_HEADS + h) * SEQ + s1) * DK + kd) = v1;
            } else {
                *(float2*)(out + (size_t)r0 * D_MODEL + c) = v0;
                *(float2*)(out + (size_t)r1 * D_MODEL + c) = v1;
            }
        }
    }
}

// proj wrapper: grid.z selects Q/K/V
struct ProjArgs {
    const float* X[3];
    const float* W[3];
    const float* bias[3];
    float* out[3];
};

__global__ __launch_bounds__(256, 2) void proj_gemm3_v2_kernel(ProjArgs args)
{
    extern __shared__ uint32_t sg[];
    // identical body via tail-call style: re-dispatch is awkward; inline MODE 0 logic
    const int z = blockIdx.z;
    const float* X    = args.X[z];
    const float* W    = args.W[z];
    const float* bias = args.bias[z];
    float* out        = args.out[z];

    uint32_t* smA = sg;
    uint32_t* smB = sg + NSTAGE * A_STAGE_WORDS;

    const int t    = threadIdx.x;
    const int n0   = blockIdx.x * 128;
    const int m0   = blockIdx.y * 128;
    const int warp = t >> 5;
    const int lane = t & 31;
    const int gid  = lane >> 2;
    const int tig  = lane & 3;
    const int wm   = (warp & 1) * 64;
    const int wn   = (warp >> 1) * 32;

    const int am[2] = { (t + 0) >> 2, (t + 256) >> 2 };
    const int ak4   = (t & 3) << 2;

    float acc[4][4][4];
#pragma unroll
    for (int i = 0; i < 4; i++)
#pragma unroll
        for (int j = 0; j < 4; j++)
#pragma unroll
            for (int k = 0; k < 4; k++) acc[i][j][k] = 0.f;

    auto issue = [&](int stage, int kc) {
        uint32_t* As_ = smA + stage * A_STAGE_WORDS;
        uint32_t* Bs_ = smB + stage * B0_STAGE_WORDS;
#pragma unroll
        for (int rep = 0; rep < 2; rep++) {
            int m = am[rep];
            cpa16(As_ + m * A_ROW_STRIDE + ak4,
                  X + (size_t)(m0 + m) * D_MODEL + kc * 16 + ak4);
        }
#pragma unroll
        for (int rep = 0; rep < 2; rep++) {
            int f = t + rep * 256;
            int k = f >> 5, n4 = (f & 31) << 2;
            int bn = n0 + n4;
            int ck = ((k >> 2) & 3) << 2;
            cpa16(Bs_ + k * 136 + (n4 ^ ck),
                  W + (size_t)(bn >> 6) * (D_MODEL * DK)
                    + (size_t)(kc * 16 + k) * DK + (bn & 63));
        }
    };

    auto compute = [&](int stage) {
        uint32_t* As_ = smA + stage * A_STAGE_WORDS;
        uint32_t* Bs_ = smB + stage * B0_STAGE_WORDS;
#pragma unroll
        for (int ks = 0; ks < 2; ks++) {
            const int kb = ks * 8;
            const int x0 = ks ? 8 : 0;
            const int x1 = ks ? 12 : 4;
            uint32_t af[4][4];
#pragma unroll
            for (int mt = 0; mt < 4; mt++) {
                const int r = (wm + mt * 16 + gid) * A_ROW_STRIDE;
                af[mt][0] = As_[r + kb + tig];
                af[mt][1] = As_[r + 8 * A_ROW_STRIDE + kb + tig];
                af[mt][2] = As_[r + kb + tig + 4];
                af[mt][3] = As_[r + 8 * A_ROW_STRIDE + kb + tig + 4];
            }
            uint32_t bf[4][2];
#pragma unroll
            for (int nt = 0; nt < 4; nt++) {
                const int ncol = wn + nt * 8 + gid;
                bf[nt][0] = Bs_[(kb + tig) * 136 + (ncol ^ x0)];
                bf[nt][1] = Bs_[(kb + tig + 4) * 136 + (ncol ^ x1)];
            }
#pragma unroll
            for (int mt = 0; mt < 4; mt++)
#pragma unroll
                for (int nt = 0; nt < 4; nt++) mma_tf32(acc[mt][nt], af[mt], bf[nt]);
        }
    };

    issue(0, 0); cpa_commit();
    issue(1, 1); cpa_commit();
    int stage = 0;
    for (int kc = 0; kc < 64; kc++) {
        cpa_wait<1>();
        __syncthreads();
        compute(stage);
        __syncthreads();
        if (kc + 2 < 64) issue((kc + 2) % NSTAGE, kc + 2);
        cpa_commit();
        stage = (stage + 1) % NSTAGE;
    }

#pragma unroll
    for (int mt = 0; mt < 4; mt++) {
#pragma unroll
        for (int nt = 0; nt < 4; nt++) {
            const int r0 = m0 + wm + mt * 16 + gid;
            const int r1 = r0 + 8;
            const int c  = n0 + wn + nt * 8 + tig * 2;
            const float bv0 = bias[c], bv1 = bias[c + 1];
            float2 v0 = make_float2(acc[mt][nt][0] + bv0, acc[mt][nt][1] + bv1);
            float2 v1 = make_float2(acc[mt][nt][2] + bv0, acc[mt][nt][3] + bv1);
            const int h = c >> 6, kd = c & 63;
            const int b0_ = r0 >> 11, s0 = r0 & 2047;
            const int b1_ = r1 >> 11, s1 = r1 & 2047;
            *(float2*)(out + (((size_t)b0_ * NUM_HEADS + h) * SEQ + s0) * DK + kd) = v0;
            *(float2*)(out + (((size_t)b1_ * NUM_HEADS + h) * SEQ + s1) * DK + kd) = v1;
        }
    }
}

// =====================================================================
// Flash attention (R3 version, known-good 361us): tf32 mma.sync,
// Bq=128, Bkv=64, per-warp P slices, fragment-resident softmax.
// =====================================================================
__global__ __launch_bounds__(256) void flash_mma_kernel()
{
    extern __shared__ uint32_t smu[];
    uint32_t* Ks = smu;                    // [64][RSW]
    uint32_t* Vs = smu + 64 * RSW;         // [64][RSW]
    uint32_t* Ss = smu + 2 * 64 * RSW;     // [128][RSW]

    const int t    = threadIdx.x;
    const int warp = t >> 5;
    const int lane = t & 31;
    const int gid  = lane >> 2;
    const int tig  = lane & 3;
    const int q0   = blockIdx.x * 128;
    const int bh   = blockIdx.y;

    const float* qb = g_q + (size_t)bh * SEQ * DK;
    const float* kb = g_k + (size_t)bh * SEQ * DK;
    const float* vb = g_v + (size_t)bh * SEQ * DK;

    const int r0 = q0 + warp * 16 + gid;
    const int r1 = r0 + 8;
    uint32_t qf[8][4];
#pragma unroll
    for (int kk = 0; kk < 8; kk++) {
        qf[kk][0] = f2tf(qb[(size_t)r0 * DK + kk * 8 + tig]     * 0.125f);
        qf[kk][1] = f2tf(qb[(size_t)r1 * DK + kk * 8 + tig]     * 0.125f);
        qf[kk][2] = f2tf(qb[(size_t)r0 * DK + kk * 8 + tig + 4] * 0.125f);
        qf[kk][3] = f2tf(qb[(size_t)r1 * DK + kk * 8 + tig + 4] * 0.125f);
    }

    uint32_t* Sw = Ss + warp * 16 * RSW;

    float m0 = -INFINITY, m1 = -INFINITY, l0 = 0.f, l1 = 0.f;
    float o[8][4];
#pragma unroll
    for (int j = 0; j < 8; j++)
#pragma unroll
        for (int k = 0; k < 4; k++) o[j][k] = 0.f;

    for (int s0 = 0; s0 < SEQ; s0 += 64) {
        __syncthreads();
#pragma unroll
        for (int rep = 0; rep < 4; rep++) {
            int f = t + rep * 256;
            int row = f >> 4, c4 = (f & 15) << 2;
            float4 kv = *(const float4*)&kb[(size_t)(s0 + row) * DK + c4];
            float4 vv = *(const float4*)&vb[(size_t)(s0 + row) * DK + c4];
            uint4 kt = make_uint4(f2tf(kv.x), f2tf(kv.y), f2tf(kv.z), f2tf(kv.w));
            uint4 vt = make_uint4(f2tf(vv.x), f2tf(vv.y), f2tf(vv.z), f2tf(vv.w));
            *(uint4*)&Ks[row * RSW + c4] = kt;
            *(uint4*)&Vs[row * RSW + c4] = vt;
        }
        __syncthreads();

        float sacc[8][4];
#pragma unroll
        for (int j = 0; j < 8; j++)
#pragma unroll
            for (int k = 0; k < 4; k++) sacc[j][k] = 0.f;
#pragma unroll
        for (int kk = 0; kk < 8; kk++) {
            uint32_t bf[8][2];
#pragma unroll
            for (int j = 0; j < 8; j++) {
                bf[j][0] = Ks[(j * 8 + gid) * RSW + kk * 8 + tig];
                bf[j][1] = Ks[(j * 8 + gid) * RSW + kk * 8 + tig + 4];
            }
#pragma unroll
            for (int j = 0; j < 8; j++) mma_tf32(sacc[j], qf[kk], bf[j]);
        }

        float t0 = -INFINITY, t1 = -INFINITY;
#pragma unroll
        for (int j = 0; j < 8; j++) {
            t0 = fmaxf(t0, fmaxf(sacc[j][0], sacc[j][1]));
            t1 = fmaxf(t1, fmaxf(sacc[j][2], sacc[j][3]));
        }
        t0 = fmaxf(t0, __shfl_xor_sync(0xffffffffu, t0, 1));
        t0 = fmaxf(t0, __shfl_xor_sync(0xffffffffu, t0, 2));
        t1 = fmaxf(t1, __shfl_xor_sync(0xffffffffu, t1, 1));
        t1 = fmaxf(t1, __shfl_xor_sync(0xffffffffu, t1, 2));

        float nm0 = fmaxf(m0, t0), nm1 = fmaxf(m1, t1);
        float a0 = __expf(m0 - nm0), a1 = __expf(m1 - nm1);
        m0 = nm0; m1 = nm1;

        float p0 = 0.f, p1 = 0.f;
#pragma unroll
        for (int j = 0; j < 8; j++) {
            float e0 = __expf(sacc[j][0] - nm0);
            float e1 = __expf(sacc[j][1] - nm0);
            float e2 = __expf(sacc[j][2] - nm1);
            float e3 = __expf(sacc[j][3] - nm1);
            p0 += e0 + e1;
            p1 += e2 + e3;
            uint2 w0 = make_uint2(f2tf(e0), f2tf(e1));
            uint2 w1 = make_uint2(f2tf(e2), f2tf(e3));
            *(uint2*)&Sw[gid * RSW + j * 8 + tig * 2]       = w0;
            *(uint2*)&Sw[(gid + 8) * RSW + j * 8 + tig * 2] = w1;
        }
        p0 += __shfl_xor_sync(0xffffffffu, p0, 1);
        p0 += __shfl_xor_sync(0xffffffffu, p0, 2);
        p1 += __shfl_xor_sync(0xffffffffu, p1, 1);
        p1 += __shfl_xor_sync(0xffffffffu, p1, 2);
        l0 = l0 * a0 + p0;
        l1 = l1 * a1 + p1;

#pragma unroll
        for (int j = 0; j < 8; j++) {
            o[j][0] *= a0; o[j][1] *= a0;
            o[j][2] *= a1; o[j][3] *= a1;
        }
        __syncwarp();

#pragma unroll
        for (int kk = 0; kk < 8; kk++) {
            uint32_t af[4];
            af[0] = Sw[gid * RSW + kk * 8 + tig];
            af[1] = Sw[(gid + 8) * RSW + kk * 8 + tig];
            af[2] = Sw[gid * RSW + kk * 8 + tig + 4];
            af[3] = Sw[(gid + 8) * RSW + kk * 8 + tig + 4];
#pragma unroll
            for (int j = 0; j < 8; j++) {
                uint32_t bf[2];
                bf[0] = Vs[(kk * 8 + tig) * RSW + j * 8 + gid];
                bf[1] = Vs[(kk * 8 + tig + 4) * RSW + j * 8 + gid];
                mma_tf32(o[j], af, bf);
            }
        }
        __syncwarp();
    }

    const float i0 = 1.f / l0, i1 = 1.f / l1;
    const int b_ = bh >> 4, h = bh & 15;
    float* row0 = g_cat + (size_t)(b_ * SEQ + r0) * D_MODEL + h * DK;
    float* row1 = g_cat + (size_t)(b_ * SEQ + r1) * D_MODEL + h * DK;
#pragma unroll
    for (int j = 0; j < 8; j++) {
        *(float2*)(row0 + j * 8 + tig * 2) = make_float2(o[j][0] * i0, o[j][1] * i0);
        *(float2*)(row1 + j * 8 + tig * 2) = make_float2(o[j][2] * i1, o[j][3] * i1);
    }
}

extern "C" void kernel_launch(void* const* d_in, const int* in_sizes, int n_in,
                              void* d_out, int out_size)
{
    const float* Q  = (const float*)d_in[0];
    const float* K  = (const float*)d_in[1];
    const float* V  = (const float*)d_in[2];
    const float* Wq = (const float*)d_in[3];
    const float* bq = (const float*)d_in[4];
    const float* Wk = (const float*)d_in[5];
    const float* bk = (const float*)d_in[6];
    const float* Wv = (const float*)d_in[7];
    const float* bv = (const float*)d_in[8];
    const float* Wo = (const float*)d_in[9];
    const float* bo = (const float*)d_in[10];
    float* out = (float*)d_out;

    float *gq, *gk, *gv, *gcat;
    cudaGetSymbolAddress((void**)&gq, g_q);
    cudaGetSymbolAddress((void**)&gk, g_k);
    cudaGetSymbolAddress((void**)&gv, g_v);
    cudaGetSymbolAddress((void**)&gcat, g_cat);

    const int proj_smem = (NSTAGE * A_STAGE_WORDS + NSTAGE * B0_STAGE_WORDS) * 4; // 56832
    const int outg_smem = (NSTAGE * A_STAGE_WORDS + NSTAGE * B1_STAGE_WORDS) * 4; // 61440
    const int flash_smem = (64 + 64 + 128) * RSW * 4;                             // 69632

    cudaFuncSetAttribute(proj_gemm3_v2_kernel,
                         cudaFuncAttributeMaxDynamicSharedMemorySize, proj_smem);
    cudaFuncSetAttribute(gemm_v2_kernel<1>,
                         cudaFuncAttributeMaxDynamicSharedMemorySize, outg_smem);
    cudaFuncSetAttribute(flash_mma_kernel,
                         cudaFuncAttributeMaxDynamicSharedMemorySize, flash_smem);

    ProjArgs pa;
    pa.X[0] = Q;  pa.X[1] = K;  pa.X[2] = V;
    pa.W[0] = Wq; pa.W[1] = Wk; pa.W[2] = Wv;
    pa.bias[0] = bq; pa.bias[1] = bk; pa.bias[2] = bv;
    pa.out[0] = gq; pa.out[1] = gk; pa.out[2] = gv;

    dim3 gblk(256);
    dim3 pgrd(D_MODEL / 128, M_TOTAL / 128, 3);  // (8, 32, 3)
    proj_gemm3_v2_kernel<<<pgrd, gblk, proj_smem>>>(pa);

    dim3 fgrd(SEQ / 128, BATCH * NUM_HEADS);     // (16, 32)
    flash_mma_kernel<<<fgrd, gblk, flash_smem>>>();

    dim3 ogrd(D_MODEL / 128, M_TOTAL / 128);     // (8, 32)
    gemm_v2_kernel<1><<<ogrd, gblk, outg_smem>>>(gcat, Wo, bo, out);
}